// round 16
// baseline (speedup 1.0000x reference)
#include <cuda_runtime.h>
#include <cuda_bf16.h>
#include <cstdint>

#define HH 56
#define WW 56
#define HWSZ 3136
#define XSTRB 401408
#define NELEM 6422528
#define PIMG 3364            // 58*58 padded image
#define NP 53824             // 16*3364
#define MPAD 53888           // 421*128
#define NT 421
#define NSM 148
#define ROWS_BUF (MPAD + 128) // 64 guard rows front + 128 back-pad/guard
#define NPVALID 50176.0f     // 16*56*56 real pixels
#define ROWB 144             // 64 bf16 (128B) + 16B pad
#define TILE_B (128 * ROWB)  // 18432
#define STAGE_B (4 * TILE_B) // 73728: B, A1, A2, A3
#define SMEM_CONV (2 * STAGE_B)   // 147456
#define NITER 18             // 9 taps * 2 k64-halves per tile

// ---------------- device scratch ----------------
__device__ __align__(16) __nv_bfloat16 g_wb1[9*128*128];   // [k][o][c] integer weights
__device__ __align__(16) __nv_bfloat16 g_wb2[9*128*128];
__device__ __align__(16) __nv_bfloat16 g_a1[ROWS_BUF*128]; // activation split terms [n'+64][c]
__device__ __align__(16) __nv_bfloat16 g_a2[ROWS_BUF*128];
__device__ __align__(16) __nv_bfloat16 g_a3[ROWS_BUF*128];
__device__ float g_t1[MPAD*128];             // conv pre-BN outputs [n'][o]
__device__ float g_t2[MPAD*128];
__device__ float g_sum1[128], g_sq1[128], g_sum2[128], g_sq2[128];

// ---------------- PTX helpers ----------------
static __device__ __forceinline__ uint32_t smem_u32(const void* p) {
    uint32_t a;
    asm("{ .reg .u64 t; cvta.to.shared.u64 t, %1; cvt.u32.u64 %0, t; }" : "=r"(a) : "l"(p));
    return a;
}
static __device__ __forceinline__ void cp16(uint32_t dst, const void* src) {
    asm volatile("cp.async.cg.shared.global [%0], [%1], 16;" :: "r"(dst), "l"(src) : "memory");
}
static __device__ __forceinline__ void cp_commit() {
    asm volatile("cp.async.commit_group;" ::: "memory");
}
template <int N> static __device__ __forceinline__ void cp_wait() {
    asm volatile("cp.async.wait_group %0;" :: "n"(N) : "memory");
}
static __device__ __forceinline__ void ldsm_x4(uint32_t& r0, uint32_t& r1, uint32_t& r2,
                                               uint32_t& r3, uint32_t addr) {
    asm volatile("ldmatrix.sync.aligned.m8n8.x4.shared.b16 {%0,%1,%2,%3},[%4];"
                 : "=r"(r0), "=r"(r1), "=r"(r2), "=r"(r3) : "r"(addr));
}
static __device__ __forceinline__ void mma16816(float* c, const uint32_t* a,
                                                uint32_t b0, uint32_t b1) {
    asm volatile("mma.sync.aligned.m16n8k16.row.col.f32.bf16.bf16.f32 "
                 "{%0,%1,%2,%3},{%4,%5,%6,%7},{%8,%9},{%0,%1,%2,%3};"
                 : "+f"(c[0]), "+f"(c[1]), "+f"(c[2]), "+f"(c[3])
                 : "r"(a[0]), "r"(a[1]), "r"(a[2]), "r"(a[3]), "r"(b0), "r"(b1));
}

// ---------------- BN param compute (inline helper) ----------------
static __device__ __forceinline__ void bn_params(const float* sum, const float* sq,
                                                 const float* g, const float* bv, int c,
                                                 float& s, float& bb)
{
    float m   = __fdiv_rn(__ldg(sum + c), NPVALID);
    float var = fmaxf(__fdiv_rn(__ldg(sq + c), NPVALID) - m * m, 0.f);
    s  = __fdiv_rn(__ldg(g + c), sqrtf(var + 1e-5f));
    bb = __ldg(bv + c) - m * s;
}

// ---------------- fused prep: weights (blocks 0..1151) + x split (1152..2087) ----------------
__global__ void prep_kernel(const float* __restrict__ x,
                            const float* __restrict__ w1, const float* __restrict__ wa1,
                            const float* __restrict__ w2, const float* __restrict__ wa2)
{
    __shared__ float s[128 * 57];
    int bid = blockIdx.x;
    if (bid < 1152) {                      // ---- weight quantize + stat zero ----
        if (bid == 0 && threadIdx.x < 128) {
            int t = threadIdx.x;
            g_sum1[t] = 0.f; g_sq1[t] = 0.f; g_sum2[t] = 0.f; g_sq2[t] = 0.f;
        }
        int idx = bid * 256 + threadIdx.x;
        if (idx < 2 * 9 * 128 * 128) {
            int layer = idx / 147456;
            int r = idx - layer * 147456;
            int k = r >> 14, o = (r >> 7) & 127, c = r & 127;
            const float* w  = layer ? w2  : w1;
            const float* wa = layer ? wa2 : wa1;
            float v = __fdiv_rn(w[(k << 14) + (o << 7) + c], wa[k]);
            v = rintf(fminf(fmaxf(v, -4.f), 3.f));
            (layer ? g_wb2 : g_wb1)[(k << 14) + (o << 7) + c] = __float2bfloat16(v);
        }
        return;
    }
    bid -= 1152;
    if (bid < 928) {                       // ---- (b, hp) padded image row split ----
        int b = bid / 58, hp = bid % 58;
        if (hp >= 1 && hp <= 56) {
            for (int i = threadIdx.x; i < 128 * 56; i += 256) {
                int c = i / 56, w = i - c * 56;
                s[c * 57 + w] = __ldg(x + b * XSTRB + c * HWSZ + (hp - 1) * WW + w);
            }
        }
        __syncthreads();
        int np = b * PIMG + hp * 58;
        for (int i = threadIdx.x; i < 58 * 128; i += 256) {
            int px = i >> 7, c = i & 127;
            float v = 0.f;
            if (hp >= 1 && hp <= 56 && px >= 1 && px <= 56) v = s[c * 57 + (px - 1)];
            __nv_bfloat16 h1 = __float2bfloat16(v);
            float r1 = v - __bfloat162float(h1);
            __nv_bfloat16 h2 = __float2bfloat16(r1);
            float r2 = r1 - __bfloat162float(h2);
            __nv_bfloat16 h3 = __float2bfloat16(r2);
            int o = (np + px + 64) * 128 + c;
            g_a1[o] = h1; g_a2[o] = h2; g_a3[o] = h3;
        }
    } else {                               // ---- zero guard + tile-pad rows ----
        int z0 = (bid - 928) * 24;
        for (int i = threadIdx.x; i < 24 * 128; i += 256) {
            int z = z0 + (i >> 7), c = i & 127;
            int r = (z < 64) ? z : (NP + z);
            __nv_bfloat16 zv = __float2bfloat16(0.f);
            g_a1[r * 128 + c] = zv; g_a2[r * 128 + c] = zv; g_a3[r * 128 + c] = zv;
        }
    }
}

// ---------------- bn1 (block-shared finalize) + relu + mask + split ----------------
__global__ void bnsplit_kernel(const float* __restrict__ g1, const float* __restrict__ b1)
{
    __shared__ float ssc[128], sbb[128];
    int t = threadIdx.x;
    if (t < 128) bn_params(g_sum1, g_sq1, g1, b1, t, ssc[t], sbb[t]);
    __syncthreads();
    int r = blockIdx.x * 2 + (t >> 7);
    int c = t & 127;
    int np = r - 64;
    float v = 0.f;
    if (np >= 0 && np < NP) {
        int rp = np % PIMG;
        int hp = rp / 58, wp = rp - hp * 58;
        if (hp >= 1 && hp <= 56 && wp >= 1 && wp <= 56)
            v = fmaxf(fmaf(g_t1[np * 128 + c], ssc[c], sbb[c]), 0.f);
    }
    __nv_bfloat16 h1 = __float2bfloat16(v);
    float r1 = v - __bfloat162float(h1);
    __nv_bfloat16 h2 = __float2bfloat16(r1);
    float r2 = r1 - __bfloat162float(h2);
    __nv_bfloat16 h3 = __float2bfloat16(r2);
    int o = r * 128 + c;
    g_a1[o] = h1; g_a2[o] = h2; g_a3[o] = h3;
}

// ---------------- stage loader: B + 3 A-term tiles (each 128x64 bf16) ----------------
static __device__ __forceinline__ void load_stage(int it, uint32_t sbase, int m0,
                                                  const __nv_bfloat16* wb, int t)
{
    const int tap = it >> 1, half = it & 1;
    const int c0 = half << 6;
    const int tapoff = (tap % 3 - 1) * 58 + (tap / 3 - 1);
    const __nv_bfloat16* srcs[4];
    srcs[0] = wb + (tap << 14) + c0;
    srcs[1] = g_a1 + (size_t)(m0 + tapoff + 64) * 128 + c0;
    srcs[2] = g_a2 + (size_t)(m0 + tapoff + 64) * 128 + c0;
    srcs[3] = g_a3 + (size_t)(m0 + tapoff + 64) * 128 + c0;
#pragma unroll
    for (int tile = 0; tile < 4; tile++) {
        const __nv_bfloat16* src = srcs[tile];
        uint32_t dst = sbase + tile * TILE_B;
#pragma unroll
        for (int p = 0; p < 2; p++) {
            int v = t + (p << 9);          // 0..1023
            int row = v >> 3, col = v & 7;
            cp16(dst + row * ROWB + col * 16, src + (size_t)row * 128 + col * 8);
        }
    }
    cp_commit();
}

// ---------------- conv: persistent warp-MMA split conv, cross-tile pipeline ----------------
template <int LAYER>
__global__ __launch_bounds__(512, 1)
void conv_kernel(const float* __restrict__ wa, const float* __restrict__ pa)
{
    extern __shared__ __align__(16) char dsm[];
    __shared__ float sRed[2][128];
    uint32_t sm0 = smem_u32(dsm);
    const int t = threadIdx.x, wid = t >> 5, lane = t & 31;
    const int wm = wid & 3, wn = wid >> 2;          // 4x4 warp grid, 32x32 tiles
    const int bid = blockIdx.x;
    const __nv_bfloat16* wb = (LAYER == 1) ? g_wb1 : g_wb2;
    float* tout = (LAYER == 1) ? g_t1 : g_t2;
    float* gsum = (LAYER == 1) ? g_sum1 : g_sum2;
    float* gsq  = (LAYER == 1) ? g_sq1  : g_sq2;

    const int ntile = (NT - bid + NSM - 1) / NSM;   // 2 or 3
    const int G = ntile * NITER;

    float psum[2][4][4];
    float acc [2][4][4];
#pragma unroll
    for (int mi = 0; mi < 2; mi++)
#pragma unroll
        for (int nq = 0; nq < 4; nq++)
#pragma unroll
            for (int e = 0; e < 4; e++) { psum[mi][nq][e] = 0.f; acc[mi][nq][e] = 0.f; }

    // ldmatrix lane bases (within a tile)
    const uint32_t aOff = (uint32_t)(wm * 32 + (lane & 15)) * ROWB + ((lane >> 4) << 4);
    const uint32_t bOff = (uint32_t)(wn * 32 + (lane & 7) + ((lane >> 4) << 3)) * ROWB
                          + (((lane >> 3) & 1) << 4);

    load_stage(0, sm0, bid << 7, wb, t);

#pragma unroll 1
    for (int g = 0; g < G; g++) {
        const int it = g % NITER;
        cp_wait<0>();
        __syncthreads();                   // stage g visible; prior compute done
        if (g + 1 < G) {
            int g1 = g + 1;
            int m0n = (bid + (g1 / NITER) * NSM) << 7;
            load_stage(g1 % NITER, sm0 + (g1 & 1) * STAGE_B, m0n, wb, t);
        }

        const uint32_t stg = sm0 + (g & 1) * STAGE_B;
        const uint32_t bA = stg + bOff;

#pragma unroll
        for (int kt = 0; kt < 4; kt++) {
            uint32_t b[2][4];
#pragma unroll
            for (int nj = 0; nj < 2; nj++)
                ldsm_x4(b[nj][0], b[nj][1], b[nj][2], b[nj][3],
                        bA + nj * 16 * ROWB + kt * 32);
#pragma unroll
            for (int term = 0; term < 3; term++) {
                const uint32_t aA = stg + (1 + term) * TILE_B + aOff;
                uint32_t a[2][4];
#pragma unroll
                for (int mi = 0; mi < 2; mi++)
                    ldsm_x4(a[mi][0], a[mi][1], a[mi][2], a[mi][3],
                            aA + mi * 16 * ROWB + kt * 32);
#pragma unroll
                for (int mi = 0; mi < 2; mi++)
#pragma unroll
                    for (int nq = 0; nq < 4; nq++)
                        mma16816(psum[mi][nq], a[mi], b[nq >> 1][(nq & 1) * 2],
                                 b[nq >> 1][(nq & 1) * 2 + 1]);
            }
        }

        if (it & 1) {                       // tap boundary: LSQ quantize psum -> acc
            int tap = it >> 1;
            float ak = __ldg(wa + tap), pk = __ldg(pa + tap);
#pragma unroll
            for (int mi = 0; mi < 2; mi++)
#pragma unroll
                for (int nq = 0; nq < 4; nq++)
#pragma unroll
                    for (int e = 0; e < 4; e++) {
                        float v = __fdiv_rn(__fmul_rn(psum[mi][nq][e], ak), pk);
                        v = fminf(fmaxf(v, -128.f), 127.f);
                        acc[mi][nq][e] = __fadd_rn(acc[mi][nq][e], __fmul_rn(rintf(v), pk));
                        psum[mi][nq][e] = 0.f;
                    }
        }

        if (it == NITER - 1) {              // ---- tile complete: store + stats ----
            const int m0 = (bid + (g / NITER) * NSM) << 7;
#pragma unroll
            for (int mi = 0; mi < 2; mi++) {
                int row0 = m0 + wm * 32 + mi * 16 + (lane >> 2);
#pragma unroll
                for (int nq = 0; nq < 4; nq++) {
                    int col = wn * 32 + nq * 8 + (lane & 3) * 2;
                    *reinterpret_cast<float2*>(tout + (size_t)row0 * 128 + col) =
                        make_float2(acc[mi][nq][0], acc[mi][nq][1]);
                    *reinterpret_cast<float2*>(tout + (size_t)(row0 + 8) * 128 + col) =
                        make_float2(acc[mi][nq][2], acc[mi][nq][3]);
                }
            }
            if (t < 128) { sRed[0][t] = 0.f; sRed[1][t] = 0.f; }
            __syncthreads();
#pragma unroll
            for (int mi = 0; mi < 2; mi++) {
#pragma unroll
                for (int rr = 0; rr < 2; rr++) {
                    int np = m0 + wm * 32 + mi * 16 + (lane >> 2) + rr * 8;
                    int rp = np % PIMG;
                    int hp = rp / 58, wp = rp - hp * 58;
                    float msk = ((np < NP) && hp >= 1 && hp <= 56 && wp >= 1 && wp <= 56) ? 1.f : 0.f;
#pragma unroll
                    for (int nq = 0; nq < 4; nq++)
#pragma unroll
                        for (int e2 = 0; e2 < 2; e2++) {
                            float v = acc[mi][nq][rr * 2 + e2] * msk;
                            float sv = v, qv = v * v;
#pragma unroll
                            for (int d = 4; d <= 16; d <<= 1) {
                                sv += __shfl_xor_sync(0xffffffffu, sv, d);
                                qv += __shfl_xor_sync(0xffffffffu, qv, d);
                            }
                            if (lane < 4) {
                                int col = wn * 32 + nq * 8 + lane * 2 + e2;
                                atomicAdd(&sRed[0][col], sv);
                                atomicAdd(&sRed[1][col], qv);
                            }
                        }
                }
            }
            __syncthreads();
            if (t < 128) {
                atomicAdd(gsum + t, sRed[0][t]);
                atomicAdd(gsq + t,  sRed[1][t]);
            }
#pragma unroll
            for (int mi = 0; mi < 2; mi++)
#pragma unroll
                for (int nq = 0; nq < 4; nq++)
#pragma unroll
                    for (int e = 0; e < 4; e++) acc[mi][nq][e] = 0.f;
        }
    }
}

// ---------------- final: out = relu(bn2(t2) + x), NCHW (block-shared BN2) ----------------
__global__ void final_kernel(const float* __restrict__ x, float* __restrict__ out,
                             const float* __restrict__ g2, const float* __restrict__ b2)
{
    __shared__ float s[56 * 129];
    __shared__ float ssc[128], sbb[128];
    int b = blockIdx.x / 56, h = blockIdx.x % 56;
    int np0 = b * PIMG + (h + 1) * 58 + 1;
    if (threadIdx.x < 128) bn_params(g_sum2, g_sq2, g2, b2, threadIdx.x,
                                     ssc[threadIdx.x], sbb[threadIdx.x]);
    for (int i = threadIdx.x; i < 56 * 128; i += 256) {
        int w = i >> 7, c = i & 127;
        s[w * 129 + c] = g_t2[(size_t)(np0 + w) * 128 + c];
    }
    __syncthreads();
    for (int i = threadIdx.x; i < 56 * 128; i += 256) {
        int c = i / 56, w = i - c * 56;
        int e = b * XSTRB + c * HWSZ + h * 56 + w;
        out[e] = fmaxf(fmaf(s[w * 129 + c], ssc[c], sbb[c]) + __ldg(x + e), 0.f);
    }
}

// ---------------- launch ----------------
extern "C" void kernel_launch(void* const* d_in, const int* in_sizes, int n_in,
                              void* d_out, int out_size)
{
    const float* x   = (const float*)d_in[0];
    const float* w1  = (const float*)d_in[1];
    const float* wa1 = (const float*)d_in[2];
    const float* pa1 = (const float*)d_in[3];
    const float* g1  = (const float*)d_in[4];
    const float* b1  = (const float*)d_in[5];
    const float* w2  = (const float*)d_in[6];
    const float* wa2 = (const float*)d_in[7];
    const float* pa2 = (const float*)d_in[8];
    const float* g2  = (const float*)d_in[9];
    const float* b2  = (const float*)d_in[10];
    float* out = (float*)d_out;
    (void)in_sizes; (void)n_in; (void)out_size;

    cudaFuncSetAttribute(conv_kernel<1>, cudaFuncAttributeMaxDynamicSharedMemorySize, SMEM_CONV);
    cudaFuncSetAttribute(conv_kernel<2>, cudaFuncAttributeMaxDynamicSharedMemorySize, SMEM_CONV);

    prep_kernel<<<2088, 256>>>(x, w1, wa1, w2, wa2);
    conv_kernel<1><<<NSM, 512, SMEM_CONV>>>(wa1, pa1);
    bnsplit_kernel<<<ROWS_BUF / 2, 256>>>(g1, b1);
    conv_kernel<2><<<NSM, 512, SMEM_CONV>>>(wa2, pa2);
    final_kernel<<<896, 256>>>(x, out, g2, b2);
}

// round 17
// speedup vs baseline: 1.5343x; 1.5343x over previous
#include <cuda_runtime.h>
#include <cuda_bf16.h>
#include <cstdint>

#define HH 56
#define WW 56
#define HWSZ 3136
#define XSTRB 401408
#define NELEM 6422528
#define PIMG 3364            // 58*58 padded image
#define NP 53824             // 16*3364
#define MPAD 53888           // 421*128
#define NT 421
#define ROWS_BUF (MPAD + 128) // 64 guard rows front + 128 back-pad/guard
#define NPVALID 50176.0f     // 16*56*56 real pixels
#define ROWB 144             // 64 bf16 (128B) + 16B pad
#define TILE_B (128 * ROWB)  // 18432
#define STAGE_B (4 * TILE_B) // 73728: B, A1, A2, A3
#define SMEM_CONV (2 * STAGE_B)   // 147456
#define NITER 18             // 9 taps * 2 k64-halves

// ---------------- device scratch ----------------
__device__ __align__(16) __nv_bfloat16 g_wb1[9*128*128];   // [k][o][c] integer weights
__device__ __align__(16) __nv_bfloat16 g_wb2[9*128*128];
__device__ __align__(16) __nv_bfloat16 g_a1[ROWS_BUF*128]; // activation split terms [n'+64][c]
__device__ __align__(16) __nv_bfloat16 g_a2[ROWS_BUF*128];
__device__ __align__(16) __nv_bfloat16 g_a3[ROWS_BUF*128];
__device__ float g_t1[MPAD*128];             // conv pre-BN outputs [n'][o]
__device__ float g_t2[MPAD*128];
__device__ float g_sum1[128], g_sq1[128], g_sum2[128], g_sq2[128];

// ---------------- PTX helpers ----------------
static __device__ __forceinline__ uint32_t smem_u32(const void* p) {
    uint32_t a;
    asm("{ .reg .u64 t; cvta.to.shared.u64 t, %1; cvt.u32.u64 %0, t; }" : "=r"(a) : "l"(p));
    return a;
}
static __device__ __forceinline__ void cp16(uint32_t dst, const void* src) {
    asm volatile("cp.async.cg.shared.global [%0], [%1], 16;" :: "r"(dst), "l"(src) : "memory");
}
static __device__ __forceinline__ void cp_commit() {
    asm volatile("cp.async.commit_group;" ::: "memory");
}
template <int N> static __device__ __forceinline__ void cp_wait() {
    asm volatile("cp.async.wait_group %0;" :: "n"(N) : "memory");
}
static __device__ __forceinline__ void ldsm_x4(uint32_t& r0, uint32_t& r1, uint32_t& r2,
                                               uint32_t& r3, uint32_t addr) {
    asm volatile("ldmatrix.sync.aligned.m8n8.x4.shared.b16 {%0,%1,%2,%3},[%4];"
                 : "=r"(r0), "=r"(r1), "=r"(r2), "=r"(r3) : "r"(addr));
}
static __device__ __forceinline__ void mma16816(float* c, const uint32_t* a,
                                                uint32_t b0, uint32_t b1) {
    asm volatile("mma.sync.aligned.m16n8k16.row.col.f32.bf16.bf16.f32 "
                 "{%0,%1,%2,%3},{%4,%5,%6,%7},{%8,%9},{%0,%1,%2,%3};"
                 : "+f"(c[0]), "+f"(c[1]), "+f"(c[2]), "+f"(c[3])
                 : "r"(a[0]), "r"(a[1]), "r"(a[2]), "r"(a[3]), "r"(b0), "r"(b1));
}

// ---------------- BN param compute (inline helper) ----------------
static __device__ __forceinline__ void bn_params(const float* sum, const float* sq,
                                                 const float* g, const float* bv, int c,
                                                 float& s, float& bb)
{
    float m   = __fdiv_rn(__ldg(sum + c), NPVALID);
    float var = fmaxf(__fdiv_rn(__ldg(sq + c), NPVALID) - m * m, 0.f);
    s  = __fdiv_rn(__ldg(g + c), sqrtf(var + 1e-5f));
    bb = __ldg(bv + c) - m * s;
}

// ---------------- prep: integer weights (bf16) + zero stats ----------------
__global__ void prep_kernel(const float* __restrict__ w1, const float* __restrict__ wa1,
                            const float* __restrict__ w2, const float* __restrict__ wa2)
{
    if (blockIdx.x == 0 && threadIdx.x < 128) {
        int t = threadIdx.x;
        g_sum1[t] = 0.f; g_sq1[t] = 0.f; g_sum2[t] = 0.f; g_sq2[t] = 0.f;
    }
    int idx = blockIdx.x * 256 + threadIdx.x;
    if (idx < 2 * 9 * 128 * 128) {
        int layer = idx / 147456;
        int r = idx - layer * 147456;
        int k = r >> 14, o = (r >> 7) & 127, c = r & 127;
        const float* w  = layer ? w2  : w1;
        const float* wa = layer ? wa2 : wa1;
        float v = __fdiv_rn(w[(k << 14) + (o << 7) + c], wa[k]);
        v = rintf(fminf(fmaxf(v, -4.f), 3.f));
        (layer ? g_wb2 : g_wb1)[(k << 14) + (o << 7) + c] = __float2bfloat16(v);
    }
}

// ---------------- x split: NCHW -> padded [n'][c] 3-term bf16 ----------------
__global__ void xsplit_kernel(const float* __restrict__ x)
{
    __shared__ float s[128 * 57];
    int bid = blockIdx.x;
    if (bid < 928) {                       // (b, hp) padded image row
        int b = bid / 58, hp = bid % 58;
        if (hp >= 1 && hp <= 56) {
            for (int i = threadIdx.x; i < 128 * 56; i += 256) {
                int c = i / 56, w = i - c * 56;
                s[c * 57 + w] = __ldg(x + b * XSTRB + c * HWSZ + (hp - 1) * WW + w);
            }
        }
        __syncthreads();
        int np = b * PIMG + hp * 58;
        for (int i = threadIdx.x; i < 58 * 128; i += 256) {
            int px = i >> 7, c = i & 127;
            float v = 0.f;
            if (hp >= 1 && hp <= 56 && px >= 1 && px <= 56) v = s[c * 57 + (px - 1)];
            __nv_bfloat16 h1 = __float2bfloat16(v);
            float r1 = v - __bfloat162float(h1);
            __nv_bfloat16 h2 = __float2bfloat16(r1);
            float r2 = r1 - __bfloat162float(h2);
            __nv_bfloat16 h3 = __float2bfloat16(r2);
            int o = (np + px + 64) * 128 + c;
            g_a1[o] = h1; g_a2[o] = h2; g_a3[o] = h3;
        }
    } else {                               // zero guard + tile-pad rows (192 rows)
        int z0 = (bid - 928) * 24;
        for (int i = threadIdx.x; i < 24 * 128; i += 256) {
            int z = z0 + (i >> 7), c = i & 127;
            int r = (z < 64) ? z : (NP + z);   // front guards, then back region
            __nv_bfloat16 zv = __float2bfloat16(0.f);
            g_a1[r * 128 + c] = zv; g_a2[r * 128 + c] = zv; g_a3[r * 128 + c] = zv;
        }
    }
}

// ---------------- bn1 (block-shared finalize) + relu + mask + split ----------------
__global__ void bnsplit_kernel(const float* __restrict__ g1, const float* __restrict__ b1)
{
    __shared__ float ssc[128], sbb[128];
    int t = threadIdx.x;
    if (t < 128) bn_params(g_sum1, g_sq1, g1, b1, t, ssc[t], sbb[t]);
    __syncthreads();
    int r = blockIdx.x * 2 + (t >> 7);     // buffer row
    int c = t & 127;
    int np = r - 64;
    float v = 0.f;
    if (np >= 0 && np < NP) {
        int rp = np % PIMG;
        int hp = rp / 58, wp = rp - hp * 58;
        if (hp >= 1 && hp <= 56 && wp >= 1 && wp <= 56)
            v = fmaxf(fmaf(g_t1[np * 128 + c], ssc[c], sbb[c]), 0.f);
    }
    __nv_bfloat16 h1 = __float2bfloat16(v);
    float r1 = v - __bfloat162float(h1);
    __nv_bfloat16 h2 = __float2bfloat16(r1);
    float r2 = r1 - __bfloat162float(h2);
    __nv_bfloat16 h3 = __float2bfloat16(r2);
    int o = r * 128 + c;
    g_a1[o] = h1; g_a2[o] = h2; g_a3[o] = h3;
}

// ---------------- stage loader: B + 3 A-term tiles (each 128x64 bf16) ----------------
static __device__ __forceinline__ void load_stage(int it, uint32_t sbase, int m0,
                                                  const __nv_bfloat16* wb, int t)
{
    const int tap = it >> 1, half = it & 1;
    const int c0 = half << 6;
    const int tapoff = (tap % 3 - 1) * 58 + (tap / 3 - 1);
    const __nv_bfloat16* srcs[4];
    srcs[0] = wb + (tap << 14) + c0;
    srcs[1] = g_a1 + (size_t)(m0 + tapoff + 64) * 128 + c0;
    srcs[2] = g_a2 + (size_t)(m0 + tapoff + 64) * 128 + c0;
    srcs[3] = g_a3 + (size_t)(m0 + tapoff + 64) * 128 + c0;
#pragma unroll
    for (int tile = 0; tile < 4; tile++) {
        const __nv_bfloat16* src = srcs[tile];
        uint32_t dst = sbase + tile * TILE_B;
#pragma unroll
        for (int p = 0; p < 2; p++) {
            int v = t + (p << 9);          // 0..1023
            int row = v >> 3, col = v & 7;
            cp16(dst + row * ROWB + col * 16, src + (size_t)row * 128 + col * 8);
        }
    }
    cp_commit();
}

// ---------------- conv: warp-MMA 9-tap split conv, fused BN stats ----------------
template <int LAYER>
__global__ __launch_bounds__(512, 1)
void conv_kernel(const float* __restrict__ wa, const float* __restrict__ pa)
{
    extern __shared__ __align__(16) char dsm[];
    __shared__ float sRed[2][128];
    uint32_t sm0 = smem_u32(dsm);
    const int t = threadIdx.x, wid = t >> 5, lane = t & 31;
    const int wm = wid & 3, wn = wid >> 2;          // 4x4 warp grid, 32x32 tiles
    const int m0 = blockIdx.x << 7;
    const __nv_bfloat16* wb = (LAYER == 1) ? g_wb1 : g_wb2;

    float psum[2][4][4];
    float acc [2][4][4];
#pragma unroll
    for (int mi = 0; mi < 2; mi++)
#pragma unroll
        for (int nq = 0; nq < 4; nq++)
#pragma unroll
            for (int e = 0; e < 4; e++) { psum[mi][nq][e] = 0.f; acc[mi][nq][e] = 0.f; }

    // ldmatrix lane bases (within a tile)
    const uint32_t aOff = (uint32_t)(wm * 32 + (lane & 15)) * ROWB + ((lane >> 4) << 4);
    const uint32_t bOff = (uint32_t)(wn * 32 + (lane & 7) + ((lane >> 4) << 3)) * ROWB
                          + (((lane >> 3) & 1) << 4);

    load_stage(0, sm0, m0, wb, t);

#pragma unroll 1
    for (int it = 0; it < NITER; it++) {
        cp_wait<0>();
        __syncthreads();                   // stage 'it' visible; prior compute done
        if (it + 1 < NITER)
            load_stage(it + 1, sm0 + ((it + 1) & 1) * STAGE_B, m0, wb, t);

        const uint32_t stg = sm0 + (it & 1) * STAGE_B;
        const uint32_t bA = stg + bOff;
        const uint32_t aA = stg + aOff;

#pragma unroll
        for (int kt = 0; kt < 4; kt++) {
            // ---- batch-issue ALL 8 ldsm for this kt (2 B + 6 A across terms) ----
            uint32_t b[2][4];
            uint32_t afr[3][2][4];
#pragma unroll
            for (int nj = 0; nj < 2; nj++)
                ldsm_x4(b[nj][0], b[nj][1], b[nj][2], b[nj][3],
                        bA + nj * 16 * ROWB + kt * 32);
#pragma unroll
            for (int term = 0; term < 3; term++)
#pragma unroll
                for (int mi = 0; mi < 2; mi++)
                    ldsm_x4(afr[term][mi][0], afr[term][mi][1],
                            afr[term][mi][2], afr[term][mi][3],
                            aA + (1 + term) * TILE_B + mi * 16 * ROWB + kt * 32);
            // ---- 24 MMAs with all operands resident ----
#pragma unroll
            for (int term = 0; term < 3; term++)
#pragma unroll
                for (int mi = 0; mi < 2; mi++)
#pragma unroll
                    for (int nq = 0; nq < 4; nq++)
                        mma16816(psum[mi][nq], afr[term][mi],
                                 b[nq >> 1][(nq & 1) * 2],
                                 b[nq >> 1][(nq & 1) * 2 + 1]);
        }

        if (it & 1) {                       // tap boundary: LSQ quantize psum -> acc
            int tap = it >> 1;
            float pk = __ldg(pa + tap);
            float mul = __fdiv_rn(__ldg(wa + tap), pk);   // one divide per tap
#pragma unroll
            for (int mi = 0; mi < 2; mi++)
#pragma unroll
                for (int nq = 0; nq < 4; nq++)
#pragma unroll
                    for (int e = 0; e < 4; e++) {
                        float v = __fmul_rn(psum[mi][nq][e], mul);
                        v = fminf(fmaxf(v, -128.f), 127.f);
                        acc[mi][nq][e] = __fadd_rn(acc[mi][nq][e], __fmul_rn(rintf(v), pk));
                        psum[mi][nq][e] = 0.f;
                    }
        }
        // no end-of-loop barrier — next iteration's top barrier covers WAR
    }

    // ---- store pre-BN outputs [n'][o] ----
    float* tout = (LAYER == 1) ? g_t1 : g_t2;
#pragma unroll
    for (int mi = 0; mi < 2; mi++) {
        int row0 = m0 + wm * 32 + mi * 16 + (lane >> 2);
#pragma unroll
        for (int nq = 0; nq < 4; nq++) {
            int col = wn * 32 + nq * 8 + (lane & 3) * 2;
            *reinterpret_cast<float2*>(tout + (size_t)row0 * 128 + col) =
                make_float2(acc[mi][nq][0], acc[mi][nq][1]);
            *reinterpret_cast<float2*>(tout + (size_t)(row0 + 8) * 128 + col) =
                make_float2(acc[mi][nq][2], acc[mi][nq][3]);
        }
    }

    // ---- fused BN stats (interior pixels only) ----
    if (t < 128) { sRed[0][t] = 0.f; sRed[1][t] = 0.f; }
    __syncthreads();
#pragma unroll
    for (int mi = 0; mi < 2; mi++) {
#pragma unroll
        for (int rr = 0; rr < 2; rr++) {
            int np = m0 + wm * 32 + mi * 16 + (lane >> 2) + rr * 8;
            int rp = np % PIMG;
            int hp = rp / 58, wp = rp - hp * 58;
            float msk = ((np < NP) && hp >= 1 && hp <= 56 && wp >= 1 && wp <= 56) ? 1.f : 0.f;
#pragma unroll
            for (int nq = 0; nq < 4; nq++)
#pragma unroll
                for (int e2 = 0; e2 < 2; e2++) {
                    float v = acc[mi][nq][rr * 2 + e2] * msk;
                    float sv = v, qv = v * v;
#pragma unroll
                    for (int d = 4; d <= 16; d <<= 1) {
                        sv += __shfl_xor_sync(0xffffffffu, sv, d);
                        qv += __shfl_xor_sync(0xffffffffu, qv, d);
                    }
                    if (lane < 4) {
                        int col = wn * 32 + nq * 8 + lane * 2 + e2;
                        atomicAdd(&sRed[0][col], sv);
                        atomicAdd(&sRed[1][col], qv);
                    }
                }
        }
    }
    __syncthreads();
    if (t < 128) {
        atomicAdd(((LAYER == 1) ? g_sum1 : g_sum2) + t, sRed[0][t]);
        atomicAdd(((LAYER == 1) ? g_sq1 : g_sq2) + t, sRed[1][t]);
    }
}

// ---------------- final: out = relu(bn2(t2) + x), NCHW (block-shared BN2) ----------------
__global__ void final_kernel(const float* __restrict__ x, float* __restrict__ out,
                             const float* __restrict__ g2, const float* __restrict__ b2)
{
    __shared__ float s[56 * 129];
    __shared__ float ssc[128], sbb[128];
    int b = blockIdx.x / 56, h = blockIdx.x % 56;
    int np0 = b * PIMG + (h + 1) * 58 + 1;
    if (threadIdx.x < 128) bn_params(g_sum2, g_sq2, g2, b2, threadIdx.x,
                                     ssc[threadIdx.x], sbb[threadIdx.x]);
    for (int i = threadIdx.x; i < 56 * 128; i += 256) {
        int w = i >> 7, c = i & 127;
        s[w * 129 + c] = g_t2[(size_t)(np0 + w) * 128 + c];
    }
    __syncthreads();
    for (int i = threadIdx.x; i < 56 * 128; i += 256) {
        int c = i / 56, w = i - c * 56;
        int e = b * XSTRB + c * HWSZ + h * 56 + w;
        out[e] = fmaxf(fmaf(s[w * 129 + c], ssc[c], sbb[c]) + __ldg(x + e), 0.f);
    }
}

// ---------------- launch ----------------
extern "C" void kernel_launch(void* const* d_in, const int* in_sizes, int n_in,
                              void* d_out, int out_size)
{
    const float* x   = (const float*)d_in[0];
    const float* w1  = (const float*)d_in[1];
    const float* wa1 = (const float*)d_in[2];
    const float* pa1 = (const float*)d_in[3];
    const float* g1  = (const float*)d_in[4];
    const float* b1  = (const float*)d_in[5];
    const float* w2  = (const float*)d_in[6];
    const float* wa2 = (const float*)d_in[7];
    const float* pa2 = (const float*)d_in[8];
    const float* g2  = (const float*)d_in[9];
    const float* b2  = (const float*)d_in[10];
    float* out = (float*)d_out;
    (void)in_sizes; (void)n_in; (void)out_size;

    cudaFuncSetAttribute(conv_kernel<1>, cudaFuncAttributeMaxDynamicSharedMemorySize, SMEM_CONV);
    cudaFuncSetAttribute(conv_kernel<2>, cudaFuncAttributeMaxDynamicSharedMemorySize, SMEM_CONV);

    prep_kernel<<<1152, 256>>>(w1, wa1, w2, wa2);
    xsplit_kernel<<<936, 256>>>(x);
    conv_kernel<1><<<NT, 512, SMEM_CONV>>>(wa1, pa1);
    bnsplit_kernel<<<ROWS_BUF / 2, 256>>>(g1, b1);
    conv_kernel<2><<<NT, 512, SMEM_CONV>>>(wa2, pa2);
    final_kernel<<<896, 256>>>(x, out, g2, b2);
}